// round 2
// baseline (speedup 1.0000x reference)
#include <cuda_runtime.h>
#include <cuda_bf16.h>
#include <cstdint>

// Problem constants
#define RR 4096            // rows (R)
#define CC 8               // channels
#define DD 128             // feature dim per channel
#define KK 1024            // CC*DD, fused GEMM K
#define NTILES 1024        // (4096/128)^2

// ---------------- scratch (__device__ globals: allowed) ----------------
__device__ __nv_bfloat16 g_X[RR * KK];          // 8 MB bf16 fused feature matrix
__device__ float g_N[RR];                       // fp32 row squared norms
__device__ float g_psum[NTILES];                // per-tile sum dist*S^2 (off-diag)
__device__ float g_pmax[NTILES];                // per-tile max dist (off-diag)
__device__ float g_pdiag[NTILES];               // per-tile sum S_ii^2
__device__ float g_psumS[NTILES];               // per-tile sum S
__device__ float g_pneg[NTILES];                // per-tile sum min(S,0)
__device__ float g_ppos[NTILES];                // per-tile sum max(S-1,0)

// ---------------- helpers ----------------
__device__ __forceinline__ void cp_async16(void* smem, const void* gptr) {
    uint32_t s = (uint32_t)__cvta_generic_to_shared(smem);
    asm volatile("cp.async.cg.shared.global [%0], [%1], 16;\n" :: "r"(s), "l"(gptr));
}
__device__ __forceinline__ void cp_commit() {
    asm volatile("cp.async.commit_group;\n" ::);
}
__device__ __forceinline__ void mma16816(float* c, const uint32_t* a, uint32_t b0, uint32_t b1) {
    asm volatile(
        "mma.sync.aligned.m16n8k16.row.col.f32.bf16.bf16.f32 "
        "{%0,%1,%2,%3}, {%4,%5,%6,%7}, {%8,%9}, {%0,%1,%2,%3};\n"
        : "+f"(c[0]), "+f"(c[1]), "+f"(c[2]), "+f"(c[3])
        : "r"(a[0]), "r"(a[1]), "r"(a[2]), "r"(a[3]), "r"(b0), "r"(b1));
}
__device__ __forceinline__ uint32_t lds32(const __nv_bfloat16* p) {
    return *reinterpret_cast<const uint32_t*>(p);
}

// ---------------- kernel 1: X = feat*W (bf16) + row norms ----------------
__global__ void prep_kernel(const float* __restrict__ feat, const float* __restrict__ W) {
    const int r = blockIdx.x;       // row 0..4095
    const int t = threadIdx.x;      // 0..127 (d index)
    float nrm = 0.f;
#pragma unroll
    for (int c = 0; c < CC; c++) {
        float v = feat[((size_t)c * RR + r) * DD + t] * W[c * DD + t];
        g_X[(size_t)r * KK + c * DD + t] = __float2bfloat16(v);
        nrm += v * v;
    }
#pragma unroll
    for (int o = 16; o > 0; o >>= 1) nrm += __shfl_xor_sync(0xffffffffu, nrm, o);
    __shared__ float ws[4];
    if ((t & 31) == 0) ws[t >> 5] = nrm;
    __syncthreads();
    if (t == 0) g_N[r] = ws[0] + ws[1] + ws[2] + ws[3];
}

// ---------------- kernel 2: tiled bf16 GEMM + fused dist/S epilogue ----------------
// Block tile 128x128, K-chunk 32, 256 threads (8 warps: 4 along M x 2 along N),
// warp tile 32x64, mma.sync m16n8k16 bf16->fp32.
__global__ __launch_bounds__(256) void tile_kernel(const float* __restrict__ S,
                                                   float* __restrict__ outS) {
    constexpr int BK = 32;
    constexpr int STR = 40;     // smem row stride (bf16 elems) — conflict-free pad
    constexpr int NK = KK / BK; // 32

    __shared__ __align__(16) __nv_bfloat16 Ash[2][128 * STR];
    __shared__ __align__(16) __nv_bfloat16 Bsh[2][128 * STR];
    __shared__ float red[8][6];

    const int tid = threadIdx.x;
    const int ti = blockIdx.y, tj = blockIdx.x;
    const int rowBase = ti * 128, colBase = tj * 128;
    const __nv_bfloat16* __restrict__ Ag = g_X + (size_t)rowBase * KK;
    const __nv_bfloat16* __restrict__ Bg = g_X + (size_t)colBase * KK;

    const int wid = tid >> 5, lane = tid & 31;
    const int wm = wid & 3;       // 0..3 -> M offset wm*32
    const int wn = wid >> 2;      // 0..1 -> N offset wn*64
    const int g = lane >> 2, tg = lane & 3;

    float acc[2][8][4];
#pragma unroll
    for (int m = 0; m < 2; m++)
#pragma unroll
        for (int n = 0; n < 8; n++)
#pragma unroll
            for (int k = 0; k < 4; k++) acc[m][n][k] = 0.f;

    // stage loader: 128 rows x 32 cols bf16 = 512 x 16B chunks, 2 per thread per matrix
    auto issue = [&](int kt, int buf) {
        const int k0 = kt * BK;
#pragma unroll
        for (int i = 0; i < 2; i++) {
            const int q = tid + i * 256;      // 0..511
            const int row = q >> 2, cchunk = q & 3;
            cp_async16(&Ash[buf][row * STR + cchunk * 8], Ag + (size_t)row * KK + k0 + cchunk * 8);
            cp_async16(&Bsh[buf][row * STR + cchunk * 8], Bg + (size_t)row * KK + k0 + cchunk * 8);
        }
        cp_commit();
    };

    issue(0, 0);
    for (int kt = 0; kt < NK; kt++) {
        const int buf = kt & 1;
        if (kt + 1 < NK) {
            issue(kt + 1, buf ^ 1);
            asm volatile("cp.async.wait_group 1;\n" ::);
        } else {
            asm volatile("cp.async.wait_group 0;\n" ::);
        }
        __syncthreads();

#pragma unroll
        for (int ks = 0; ks < 2; ks++) {
            const int k0 = ks * 16;
            uint32_t a[2][4];
#pragma unroll
            for (int mm = 0; mm < 2; mm++) {
                const __nv_bfloat16* p = &Ash[buf][(wm * 32 + mm * 16 + g) * STR + k0 + 2 * tg];
                a[mm][0] = lds32(p);
                a[mm][1] = lds32(p + 8 * STR);
                a[mm][2] = lds32(p + 8);
                a[mm][3] = lds32(p + 8 * STR + 8);
            }
#pragma unroll
            for (int nn = 0; nn < 8; nn++) {
                const __nv_bfloat16* p = &Bsh[buf][(wn * 64 + nn * 8 + g) * STR + k0 + 2 * tg];
                const uint32_t b0 = lds32(p), b1 = lds32(p + 8);
#pragma unroll
                for (int mm = 0; mm < 2; mm++) mma16816(acc[mm][nn], a[mm], b0, b1);
            }
        }
        __syncthreads();
    }

    // ---- fused epilogue: dist, S^2 weighting, penalties, S copy ----
    float lsum = 0.f, lmax = 0.f, ldiag = 0.f, lS = 0.f, lneg = 0.f, lpos = 0.f;

    float Njv[16];
#pragma unroll
    for (int nn = 0; nn < 8; nn++)
#pragma unroll
        for (int cc2 = 0; cc2 < 2; cc2++)
            Njv[nn * 2 + cc2] = g_N[colBase + wn * 64 + nn * 8 + 2 * tg + cc2];

#pragma unroll
    for (int mm = 0; mm < 2; mm++) {
#pragma unroll
        for (int rr = 0; rr < 2; rr++) {
            const int grow = rowBase + wm * 32 + mm * 16 + g + rr * 8;
            const float Ni = g_N[grow];
#pragma unroll
            for (int nn = 0; nn < 8; nn++) {
#pragma unroll
                for (int cc2 = 0; cc2 < 2; cc2++) {
                    const int gcol = colBase + wn * 64 + nn * 8 + 2 * tg + cc2;
                    const float Gv = acc[mm][nn][rr * 2 + cc2];
                    const float d = fmaxf(Ni + Njv[nn * 2 + cc2] - 2.f * Gv, 0.f);
                    const size_t idx = (size_t)grow * RR + gcol;
                    const float s = S[idx];
                    outS[idx] = s;
                    lS += s;
                    if (s < 0.f) lneg += s;
                    if (s > 1.f) lpos += s - 1.f;
                    if (grow == gcol) {
                        ldiag += s * s;
                    } else {
                        lsum += d * s * s;
                        lmax = fmaxf(lmax, d);
                    }
                }
            }
        }
    }

    // block reduction (deterministic, no atomics)
#pragma unroll
    for (int o = 16; o > 0; o >>= 1) {
        lsum += __shfl_xor_sync(0xffffffffu, lsum, o);
        lmax = fmaxf(lmax, __shfl_xor_sync(0xffffffffu, lmax, o));
        ldiag += __shfl_xor_sync(0xffffffffu, ldiag, o);
        lS += __shfl_xor_sync(0xffffffffu, lS, o);
        lneg += __shfl_xor_sync(0xffffffffu, lneg, o);
        lpos += __shfl_xor_sync(0xffffffffu, lpos, o);
    }
    if (lane == 0) {
        red[wid][0] = lsum; red[wid][1] = lmax; red[wid][2] = ldiag;
        red[wid][3] = lS;   red[wid][4] = lneg; red[wid][5] = lpos;
    }
    __syncthreads();
    if (tid == 0) {
        float s0 = 0, m0 = 0, d0 = 0, t0 = 0, n0 = 0, p0 = 0;
#pragma unroll
        for (int w = 0; w < 8; w++) {
            s0 += red[w][0]; m0 = fmaxf(m0, red[w][1]); d0 += red[w][2];
            t0 += red[w][3]; n0 += red[w][4]; p0 += red[w][5];
        }
        const int tileIdx = ti * gridDim.x + tj;
        g_psum[tileIdx] = s0; g_pmax[tileIdx] = m0; g_pdiag[tileIdx] = d0;
        g_psumS[tileIdx] = t0; g_pneg[tileIdx] = n0; g_ppos[tileIdx] = p0;
    }
}

// ---------------- kernel 3: final reduction + loss + W copy ----------------
__global__ void final_kernel(const float* __restrict__ W, float* __restrict__ out) {
    const int t = threadIdx.x;   // 0..1023
    // copy W verbatim to output tail
    const float w = W[t];
    out[1 + (size_t)RR * RR + t] = w;

    float ps = g_psum[t], pm = g_pmax[t], pd = g_pdiag[t];
    float pS = g_psumS[t], pn = g_pneg[t], pp = g_ppos[t];
    float pw = w;

    __shared__ float sh[32][7];
#pragma unroll
    for (int o = 16; o > 0; o >>= 1) {
        ps += __shfl_xor_sync(0xffffffffu, ps, o);
        pm = fmaxf(pm, __shfl_xor_sync(0xffffffffu, pm, o));
        pd += __shfl_xor_sync(0xffffffffu, pd, o);
        pS += __shfl_xor_sync(0xffffffffu, pS, o);
        pn += __shfl_xor_sync(0xffffffffu, pn, o);
        pp += __shfl_xor_sync(0xffffffffu, pp, o);
        pw += __shfl_xor_sync(0xffffffffu, pw, o);
    }
    if ((t & 31) == 0) {
        const int wi = t >> 5;
        sh[wi][0] = ps; sh[wi][1] = pm; sh[wi][2] = pd; sh[wi][3] = pS;
        sh[wi][4] = pn; sh[wi][5] = pp; sh[wi][6] = pw;
    }
    __syncthreads();
    if (t == 0) {
        double sum = 0, diag2 = 0, sumS = 0, neg = 0, pos = 0, sumW = 0;
        float dmax = 0.f;
        for (int w2 = 0; w2 < 32; w2++) {
            sum += (double)sh[w2][0];
            dmax = fmaxf(dmax, sh[w2][1]);
            diag2 += (double)sh[w2][2];
            sumS += (double)sh[w2][3];
            neg += (double)sh[w2][4];
            pos += (double)sh[w2][5];
            sumW += (double)sh[w2][6];
        }
        const double dist_S = sum + (double)dmax * diag2;
        const double pW = 100.0 * fabs(sumW - 128.0);   // sum over axis0 minus 1 per col, summed
        const double pSs = 100.0 * fabs(sumS - 4096.0);
        const double pen = -neg + pos;                   // BETA = 1
        out[0] = (float)(dist_S + pen + pW + pSs);
    }
}

// ---------------- launch ----------------
extern "C" void kernel_launch(void* const* d_in, const int* in_sizes, int n_in,
                              void* d_out, int out_size) {
    const float* feat = (const float*)d_in[0];   // (8,4096,128)
    const float* S    = (const float*)d_in[1];   // (4096,4096)
    const float* W    = (const float*)d_in[2];   // (8,1,128)
    float* out = (float*)d_out;                  // [loss | S | W]

    prep_kernel<<<RR, 128>>>(feat, W);
    dim3 grid(RR / 128, RR / 128);               // (32,32)
    tile_kernel<<<grid, 256>>>(S, out + 1);
    final_kernel<<<1, 1024>>>(W, out);
}

// round 5
// speedup vs baseline: 1.2783x; 1.2783x over previous
#include <cuda_runtime.h>
#include <cuda_bf16.h>
#include <cstdint>

// Problem constants
#define RR 4096            // rows (R)
#define CC 8               // channels
#define DD 128             // feature dim per channel
#define KK 1024            // CC*DD, fused GEMM K
#define NT 32              // tiles per dim
#define NPAIRS 528         // NT*(NT+1)/2 upper-triangular tiles
#define NTILES 1024

// ---------------- scratch ----------------
__device__ __nv_bfloat16 g_X[RR * KK];          // 8 MB bf16 fused feature matrix
__device__ float g_N[RR];                       // fp32 row squared norms
__device__ float g_psum[NTILES];
__device__ float g_pmax[NTILES];
__device__ float g_pdiag[NTILES];
__device__ float g_psumS[NTILES];
__device__ float g_pneg[NTILES];
__device__ float g_ppos[NTILES];

// ---------------- helpers ----------------
__device__ __forceinline__ void cp_async16(void* smem, const void* gptr) {
    uint32_t s = (uint32_t)__cvta_generic_to_shared(smem);
    asm volatile("cp.async.cg.shared.global [%0], [%1], 16;\n" :: "r"(s), "l"(gptr));
}
__device__ __forceinline__ void cp_commit() {
    asm volatile("cp.async.commit_group;\n" ::);
}
__device__ __forceinline__ void mma16816(float* c, const uint32_t* a, uint32_t b0, uint32_t b1) {
    asm volatile(
        "mma.sync.aligned.m16n8k16.row.col.f32.bf16.bf16.f32 "
        "{%0,%1,%2,%3}, {%4,%5,%6,%7}, {%8,%9}, {%0,%1,%2,%3};\n"
        : "+f"(c[0]), "+f"(c[1]), "+f"(c[2]), "+f"(c[3])
        : "r"(a[0]), "r"(a[1]), "r"(a[2]), "r"(a[3]), "r"(b0), "r"(b1));
}
__device__ __forceinline__ uint32_t lds32(const __nv_bfloat16* p) {
    return *reinterpret_cast<const uint32_t*>(p);
}

// ---------------- kernel 1: X = feat*W (bf16) + row norms (vectorized) ----------------
// 256 threads = 8 warps, each warp handles one row (32 lanes x float4 = 128 elems/channel)
__global__ __launch_bounds__(256) void prep_kernel(const float* __restrict__ feat,
                                                   const float* __restrict__ W) {
    const int warp = threadIdx.x >> 5, lane = threadIdx.x & 31;
    const int r = blockIdx.x * 8 + warp;
    float nrm = 0.f;
#pragma unroll
    for (int c = 0; c < CC; c++) {
        const float4 v4 = *reinterpret_cast<const float4*>(feat + ((size_t)c * RR + r) * DD + lane * 4);
        const float4 w4 = *reinterpret_cast<const float4*>(W + c * DD + lane * 4);
        float p0 = v4.x * w4.x, p1 = v4.y * w4.y, p2 = v4.z * w4.z, p3 = v4.w * w4.w;
        nrm += p0 * p0 + p1 * p1 + p2 * p2 + p3 * p3;
        __nv_bfloat162 lo = __floats2bfloat162_rn(p0, p1);
        __nv_bfloat162 hi = __floats2bfloat162_rn(p2, p3);
        uint2 pk = make_uint2(*reinterpret_cast<uint32_t*>(&lo), *reinterpret_cast<uint32_t*>(&hi));
        *reinterpret_cast<uint2*>(&g_X[(size_t)r * KK + c * DD + lane * 4]) = pk;
    }
#pragma unroll
    for (int o = 16; o > 0; o >>= 1) nrm += __shfl_xor_sync(0xffffffffu, nrm, o);
    if (lane == 0) g_N[r] = nrm;
}

// ---------------- kernel 2: upper-tri tiled bf16 GEMM + fused epilogue ----------------
__global__ __launch_bounds__(256) void tile_kernel(const float* __restrict__ S,
                                                   float* __restrict__ outS) {
    constexpr int BK = 32;
    constexpr int STR = 40;
    constexpr int NK = KK / BK;

    __shared__ __align__(16) __nv_bfloat16 Ash[2][128 * STR];
    __shared__ __align__(16) __nv_bfloat16 Bsh[2][128 * STR];
    __shared__ float red[8][6];

    const int tid = threadIdx.x;
    // decode upper-triangular pair (ti <= tj) from linear block id
    int b = blockIdx.x;
    int ti = 0;
    {
        int rem = b;
        while (rem >= NT - ti) { rem -= NT - ti; ti++; }
        b = ti + rem;                 // b now = tj
    }
    const int tj = b;
    const int rowBase = ti * 128, colBase = tj * 128;
    const __nv_bfloat16* __restrict__ Ag = g_X + (size_t)rowBase * KK;
    const __nv_bfloat16* __restrict__ Bg = g_X + (size_t)colBase * KK;

    const int wid = tid >> 5, lane = tid & 31;
    const int wm = wid & 3;
    const int wn = wid >> 2;
    const int g = lane >> 2, tg = lane & 3;

    float acc[2][8][4];
#pragma unroll
    for (int m = 0; m < 2; m++)
#pragma unroll
        for (int n = 0; n < 8; n++)
#pragma unroll
            for (int k = 0; k < 4; k++) acc[m][n][k] = 0.f;

    auto issue = [&](int kt, int buf) {
        const int k0 = kt * BK;
#pragma unroll
        for (int i = 0; i < 2; i++) {
            const int q = tid + i * 256;
            const int row = q >> 2, cchunk = q & 3;
            cp_async16(&Ash[buf][row * STR + cchunk * 8], Ag + (size_t)row * KK + k0 + cchunk * 8);
            cp_async16(&Bsh[buf][row * STR + cchunk * 8], Bg + (size_t)row * KK + k0 + cchunk * 8);
        }
        cp_commit();
    };

    issue(0, 0);
    for (int kt = 0; kt < NK; kt++) {
        const int buf = kt & 1;
        if (kt + 1 < NK) {
            issue(kt + 1, buf ^ 1);
            asm volatile("cp.async.wait_group 1;\n" ::);
        } else {
            asm volatile("cp.async.wait_group 0;\n" ::);
        }
        __syncthreads();

#pragma unroll
        for (int ks = 0; ks < 2; ks++) {
            const int k0 = ks * 16;
            uint32_t a[2][4];
#pragma unroll
            for (int mm = 0; mm < 2; mm++) {
                const __nv_bfloat16* p = &Ash[buf][(wm * 32 + mm * 16 + g) * STR + k0 + 2 * tg];
                a[mm][0] = lds32(p);
                a[mm][1] = lds32(p + 8 * STR);
                a[mm][2] = lds32(p + 8);
                a[mm][3] = lds32(p + 8 * STR + 8);
            }
#pragma unroll
            for (int nn = 0; nn < 8; nn++) {
                const __nv_bfloat16* p = &Bsh[buf][(wn * 64 + nn * 8 + g) * STR + k0 + 2 * tg];
                const uint32_t b0 = lds32(p), b1 = lds32(p + 8);
#pragma unroll
                for (int mm = 0; mm < 2; mm++) mma16816(acc[mm][nn], a[mm], b0, b1);
            }
        }
        __syncthreads();
    }

    // ---- fused epilogue ----
    float lsum = 0.f, lmax = 0.f, ldiag = 0.f, lS = 0.f, lneg = 0.f, lpos = 0.f;
    const bool offdiag = (ti != tj);

    float Njv[16];
#pragma unroll
    for (int nn = 0; nn < 8; nn++)
#pragma unroll
        for (int cc2 = 0; cc2 < 2; cc2++)
            Njv[nn * 2 + cc2] = g_N[colBase + wn * 64 + nn * 8 + 2 * tg + cc2];

#pragma unroll
    for (int mm = 0; mm < 2; mm++) {
#pragma unroll
        for (int rr = 0; rr < 2; rr++) {
            const int grow = rowBase + wm * 32 + mm * 16 + g + rr * 8;
            const float Ni = g_N[grow];
#pragma unroll
            for (int nn = 0; nn < 8; nn++) {
#pragma unroll
                for (int cc2 = 0; cc2 < 2; cc2++) {
                    const int gcol = colBase + wn * 64 + nn * 8 + 2 * tg + cc2;
                    const float Gv = acc[mm][nn][rr * 2 + cc2];
                    const float d = fmaxf(Ni + Njv[nn * 2 + cc2] - 2.f * Gv, 0.f);
                    const size_t idx = (size_t)grow * RR + gcol;
                    const float s = S[idx];
                    outS[idx] = s;
                    lS += s;
                    if (s < 0.f) lneg += s;
                    if (s > 1.f) lpos += s - 1.f;
                    if (grow == gcol) {
                        ldiag += s * s;
                    } else {
                        lsum += d * s * s;
                        lmax = fmaxf(lmax, d);
                    }
                    if (offdiag) {
                        // mirrored element: d_ji == d_ij, handle S[j,i]
                        const size_t idx2 = (size_t)gcol * RR + grow;
                        const float s2 = S[idx2];
                        outS[idx2] = s2;
                        lS += s2;
                        if (s2 < 0.f) lneg += s2;
                        if (s2 > 1.f) lpos += s2 - 1.f;
                        lsum += d * s2 * s2;
                    }
                }
            }
        }
    }

#pragma unroll
    for (int o = 16; o > 0; o >>= 1) {
        lsum += __shfl_xor_sync(0xffffffffu, lsum, o);
        lmax = fmaxf(lmax, __shfl_xor_sync(0xffffffffu, lmax, o));
        ldiag += __shfl_xor_sync(0xffffffffu, ldiag, o);
        lS += __shfl_xor_sync(0xffffffffu, lS, o);
        lneg += __shfl_xor_sync(0xffffffffu, lneg, o);
        lpos += __shfl_xor_sync(0xffffffffu, lpos, o);
    }
    if (lane == 0) {
        red[wid][0] = lsum; red[wid][1] = lmax; red[wid][2] = ldiag;
        red[wid][3] = lS;   red[wid][4] = lneg; red[wid][5] = lpos;
    }
    __syncthreads();
    if (tid == 0) {
        float s0 = 0, m0 = 0, d0 = 0, t0 = 0, n0 = 0, p0 = 0;
#pragma unroll
        for (int w = 0; w < 8; w++) {
            s0 += red[w][0]; m0 = fmaxf(m0, red[w][1]); d0 += red[w][2];
            t0 += red[w][3]; n0 += red[w][4]; p0 += red[w][5];
        }
        const int tileIdx = blockIdx.x;
        g_psum[tileIdx] = s0; g_pmax[tileIdx] = m0; g_pdiag[tileIdx] = d0;
        g_psumS[tileIdx] = t0; g_pneg[tileIdx] = n0; g_ppos[tileIdx] = p0;
    }
}

// ---------------- kernel 3: final reduction + loss + W copy ----------------
__global__ void final_kernel(const float* __restrict__ W, float* __restrict__ out) {
    const int t = threadIdx.x;   // 0..1023
    const float w = W[t];
    out[1 + (size_t)RR * RR + t] = w;

    const bool live = (t < NPAIRS);
    float ps = live ? g_psum[t] : 0.f, pm = live ? g_pmax[t] : 0.f, pd = live ? g_pdiag[t] : 0.f;
    float pS = live ? g_psumS[t] : 0.f, pn = live ? g_pneg[t] : 0.f, pp = live ? g_ppos[t] : 0.f;
    float pw = w;

    __shared__ float sh[32][7];
#pragma unroll
    for (int o = 16; o > 0; o >>= 1) {
        ps += __shfl_xor_sync(0xffffffffu, ps, o);
        pm = fmaxf(pm, __shfl_xor_sync(0xffffffffu, pm, o));
        pd += __shfl_xor_sync(0xffffffffu, pd, o);
        pS += __shfl_xor_sync(0xffffffffu, pS, o);
        pn += __shfl_xor_sync(0xffffffffu, pn, o);
        pp += __shfl_xor_sync(0xffffffffu, pp, o);
        pw += __shfl_xor_sync(0xffffffffu, pw, o);
    }
    if ((t & 31) == 0) {
        const int wi = t >> 5;
        sh[wi][0] = ps; sh[wi][1] = pm; sh[wi][2] = pd; sh[wi][3] = pS;
        sh[wi][4] = pn; sh[wi][5] = pp; sh[wi][6] = pw;
    }
    __syncthreads();
    if (t == 0) {
        double sum = 0, diag2 = 0, sumS = 0, neg = 0, pos = 0, sumW = 0;
        float dmax = 0.f;
        for (int w2 = 0; w2 < 32; w2++) {
            sum += (double)sh[w2][0];
            dmax = fmaxf(dmax, sh[w2][1]);
            diag2 += (double)sh[w2][2];
            sumS += (double)sh[w2][3];
            neg += (double)sh[w2][4];
            pos += (double)sh[w2][5];
            sumW += (double)sh[w2][6];
        }
        const double dist_S = sum + (double)dmax * diag2;
        const double pW = 100.0 * fabs(sumW - 128.0);
        const double pSs = 100.0 * fabs(sumS - 4096.0);
        const double pen = -neg + pos;     // BETA = 1
        out[0] = (float)(dist_S + pen + pW + pSs);
    }
}

// ---------------- launch ----------------
extern "C" void kernel_launch(void* const* d_in, const int* in_sizes, int n_in,
                              void* d_out, int out_size) {
    const float* feat = (const float*)d_in[0];   // (8,4096,128)
    const float* S    = (const float*)d_in[1];   // (4096,4096)
    const float* W    = (const float*)d_in[2];   // (8,1,128)
    float* out = (float*)d_out;                  // [loss | S | W]

    prep_kernel<<<RR / 8, 256>>>(feat, W);
    tile_kernel<<<NPAIRS, 256>>>(S, out + 1);
    final_kernel<<<1, 1024>>>(W, out);
}